// round 1
// baseline (speedup 1.0000x reference)
#include <cuda_runtime.h>
#include <math.h>

// Problem constants
#define FDIM 64
#define HDIM 128
#define TILE_E 64
#define NTHREADS 256

// Shared memory layout (floats):
//  sW1   [64*128]   = 8192
//  sW2   [128*64]   = 8192
//  sWrr  [64*128]   = 8192
//  sWrc  [128*128]  = 16384
//  biases 128+64+128+128 = 448
//  sX    [64*64]    = 4096   (x, later t)
//  sH    [64*128]   = 8192   (h1, later u)
//  ints: sObs[64], sJ[64]
#define SMEM_FLOATS (8192*3 + 16384 + 448 + 4096 + 8192)
#define SMEM_BYTES  (SMEM_FLOATS*4 + 128*4)

__device__ __forceinline__ float gelu_f(float x) {
    // exact erf-based GELU (matches torch nn.GELU default / jax approximate=False)
    return 0.5f * x * (1.0f + erff(x * 0.70710678118654752440f));
}

// C-tile: 8 edges x 4 cols per thread, N=128 wide. A stride = K.
template <int K>
__device__ __forceinline__ void mm_n128(const float* __restrict__ A,
                                        const float* __restrict__ W,
                                        int e0, int c0, float acc[8][4]) {
    #pragma unroll
    for (int i = 0; i < 8; i++) { acc[i][0]=0.f; acc[i][1]=0.f; acc[i][2]=0.f; acc[i][3]=0.f; }
    #pragma unroll 2
    for (int k = 0; k < K; k += 2) {
        float4 w0 = *(const float4*)(W + k * 128 + c0);
        float4 w1 = *(const float4*)(W + (k + 1) * 128 + c0);
        #pragma unroll
        for (int i = 0; i < 8; i++) {
            float2 a = *(const float2*)(A + (e0 + i) * K + k);
            acc[i][0] = fmaf(a.y, w1.x, fmaf(a.x, w0.x, acc[i][0]));
            acc[i][1] = fmaf(a.y, w1.y, fmaf(a.x, w0.y, acc[i][1]));
            acc[i][2] = fmaf(a.y, w1.z, fmaf(a.x, w0.z, acc[i][2]));
            acc[i][3] = fmaf(a.y, w1.w, fmaf(a.x, w0.w, acc[i][3]));
        }
    }
}

// C-tile: 8 edges x 2 cols per thread, N=64 wide, K=128, A stride = 128.
__device__ __forceinline__ void mm_n64_k128(const float* __restrict__ A,
                                            const float* __restrict__ W,
                                            int e0, int c0, float acc[8][2]) {
    #pragma unroll
    for (int i = 0; i < 8; i++) { acc[i][0]=0.f; acc[i][1]=0.f; }
    #pragma unroll 2
    for (int k = 0; k < 128; k += 2) {
        float2 w0 = *(const float2*)(W + k * 64 + c0);
        float2 w1 = *(const float2*)(W + (k + 1) * 64 + c0);
        #pragma unroll
        for (int i = 0; i < 8; i++) {
            float2 a = *(const float2*)(A + (e0 + i) * 128 + k);
            acc[i][0] = fmaf(a.y, w1.x, fmaf(a.x, w0.x, acc[i][0]));
            acc[i][1] = fmaf(a.y, w1.y, fmaf(a.x, w0.y, acc[i][1]));
        }
    }
}

__global__ void __launch_bounds__(NTHREADS, 1)
attr_rel_kernel(const float* __restrict__ known_mask,
                const int*   __restrict__ obs_idx,
                const int*   __restrict__ obs_mask_idx,
                const int*   __restrict__ attr_idx,
                const float* __restrict__ obs_embs,
                const float* __restrict__ fea_corr,
                const float* __restrict__ W1,  const float* __restrict__ b1,
                const float* __restrict__ W2,  const float* __restrict__ b2,
                const float* __restrict__ Wrr, const float* __restrict__ brr,
                const float* __restrict__ Wrc, const float* __restrict__ brc,
                float* __restrict__ out, int E)
{
    extern __shared__ float smem[];
    float* sW1  = smem;
    float* sW2  = sW1  + 8192;
    float* sWrr = sW2  + 8192;
    float* sWrc = sWrr + 8192;
    float* sb1  = sWrc + 16384;
    float* sb2  = sb1  + 128;
    float* sbrr = sb2  + 64;
    float* sbrc = sbrr + 128;
    float* sX   = sbrc + 128;        // 64x64
    float* sH   = sX   + 64 * 64;    // 64x128
    int*   sObs = (int*)(sH + 64 * 128);
    int*   sJ   = sObs + 64;

    const int tid  = threadIdx.x;
    const int warp = tid >> 5;
    const int lane = tid & 31;

    // ---- one-time cooperative weight load ----
    for (int i = tid; i < 8192 / 4;  i += NTHREADS) ((float4*)sW1 )[i] = ((const float4*)W1 )[i];
    for (int i = tid; i < 8192 / 4;  i += NTHREADS) ((float4*)sW2 )[i] = ((const float4*)W2 )[i];
    for (int i = tid; i < 8192 / 4;  i += NTHREADS) ((float4*)sWrr)[i] = ((const float4*)Wrr)[i];
    for (int i = tid; i < 16384 / 4; i += NTHREADS) ((float4*)sWrc)[i] = ((const float4*)Wrc)[i];
    for (int i = tid; i < 128; i += NTHREADS) sb1[i]  = b1[i];
    for (int i = tid; i < 64;  i += NTHREADS) sb2[i]  = b2[i];
    for (int i = tid; i < 128; i += NTHREADS) sbrr[i] = brr[i];
    for (int i = tid; i < 128; i += NTHREADS) sbrc[i] = brc[i];
    __syncthreads();

    const int ntiles = (E + TILE_E - 1) / TILE_E;

    for (int tile = blockIdx.x; tile < ntiles; tile += gridDim.x) {
        const int base = tile * TILE_E;
        const int n_e  = min(TILE_E, E - base);

        // ---- stage 0: gather indices; X = softmax(m_i * m_j) in closed form ----
        {
            const int e = tid >> 2;         // edge within tile (0..63)
            const int q = tid & 3;          // quadrant: 16 features each
            const int eg = (e < n_e) ? base + e : base;
            const int row = obs_mask_idx[eg];
            const int j   = attr_idx[eg];
            if (q == 0) { sObs[e] = obs_idx[eg]; sJ[e] = j; }
            const float* mrow = known_mask + (long)row * FDIM;
            float mv[16];
            float s = 0.f;
            #pragma unroll
            for (int t = 0; t < 4; t++) {
                float4 v = *(const float4*)(mrow + q * 16 + t * 4);
                mv[t*4+0]=v.x; mv[t*4+1]=v.y; mv[t*4+2]=v.z; mv[t*4+3]=v.w;
                s += v.x + v.y + v.z + v.w;
            }
            // reduce partial sums over the 4 threads of this edge (consecutive lanes)
            s += __shfl_xor_sync(0xffffffffu, s, 1);
            s += __shfl_xor_sync(0xffffffffu, s, 2);
            const float kones = s - mrow[j];                 // ones with attr pos zeroed
            const float EULER = 2.71828182845904523536f;
            const float denom = kones * EULER + (64.0f - kones);
            const float alpha = 1.0f / denom;                // softmax value at zeros
            const float beta  = EULER * alpha;               // softmax value at ones
            #pragma unroll
            for (int t = 0; t < 16; t++) {
                const int f = q * 16 + t;
                sX[e * FDIM + f] = (mv[t] != 0.0f && f != j) ? beta : alpha;
            }
        }
        __syncthreads();

        // ---- stage 1: H = gelu(X @ W1 + b1)   [64x64]x[64x128] ----
        {
            const int e0 = warp * 8, c0 = lane * 4;
            float acc[8][4];
            mm_n128<64>(sX, sW1, e0, c0, acc);
            const float4 bb = *(const float4*)(sb1 + c0);
            #pragma unroll
            for (int i = 0; i < 8; i++) {
                float4 r;
                r.x = gelu_f(acc[i][0] + bb.x);
                r.y = gelu_f(acc[i][1] + bb.y);
                r.z = gelu_f(acc[i][2] + bb.z);
                r.w = gelu_f(acc[i][3] + bb.w);
                *(float4*)(sH + (e0 + i) * HDIM + c0) = r;
            }
        }
        __syncthreads();

        // ---- stage 2: t = fea_corr[j] * gelu(H @ W2 + b2)  -> sX ----
        {
            const int e0 = warp * 8, c0 = lane * 2;
            float acc[8][2];
            mm_n64_k128(sH, sW2, e0, c0, acc);
            const float2 bb = *(const float2*)(sb2 + c0);
            #pragma unroll
            for (int i = 0; i < 8; i++) {
                const int j = sJ[e0 + i];
                const float2 fc = *(const float2*)(fea_corr + j * FDIM + c0);
                float2 r;
                r.x = gelu_f(acc[i][0] + bb.x) * fc.x;
                r.y = gelu_f(acc[i][1] + bb.y) * fc.y;
                *(float2*)(sX + (e0 + i) * FDIM + c0) = r;
            }
        }
        __syncthreads();

        // ---- stage 3: U = obs_h * gelu(t @ Wrr + brr) -> sH ----
        {
            const int e0 = warp * 8, c0 = lane * 4;
            float acc[8][4];
            mm_n128<64>(sX, sWrr, e0, c0, acc);
            const float4 bb = *(const float4*)(sbrr + c0);
            #pragma unroll
            for (int i = 0; i < 8; i++) {
                const long oi = sObs[e0 + i];
                const float4 oh = *(const float4*)(obs_embs + oi * HDIM + c0);
                float4 r;
                r.x = gelu_f(acc[i][0] + bb.x) * oh.x;
                r.y = gelu_f(acc[i][1] + bb.y) * oh.y;
                r.z = gelu_f(acc[i][2] + bb.z) * oh.z;
                r.w = gelu_f(acc[i][3] + bb.w) * oh.w;
                *(float4*)(sH + (e0 + i) * HDIM + c0) = r;
            }
        }
        __syncthreads();

        // ---- stage 4: out = gelu(U @ Wrc + brc) -> global ----
        {
            const int e0 = warp * 8, c0 = lane * 4;
            float acc[8][4];
            mm_n128<128>(sH, sWrc, e0, c0, acc);
            const float4 bb = *(const float4*)(sbrc + c0);
            #pragma unroll
            for (int i = 0; i < 8; i++) {
                if (e0 + i < n_e) {
                    float4 r;
                    r.x = gelu_f(acc[i][0] + bb.x);
                    r.y = gelu_f(acc[i][1] + bb.y);
                    r.z = gelu_f(acc[i][2] + bb.z);
                    r.w = gelu_f(acc[i][3] + bb.w);
                    *(float4*)(out + (long)(base + e0 + i) * HDIM + c0) = r;
                }
            }
        }
        __syncthreads();
    }
}

extern "C" void kernel_launch(void* const* d_in, const int* in_sizes, int n_in,
                              void* d_out, int out_size) {
    const float* known_mask   = (const float*)d_in[0];
    const int*   obs_idx      = (const int*)  d_in[1];
    const int*   obs_mask_idx = (const int*)  d_in[2];
    const int*   attr_idx     = (const int*)  d_in[3];
    const float* obs_embs     = (const float*)d_in[4];
    const float* fea_corr     = (const float*)d_in[5];
    const float* W1  = (const float*)d_in[6];
    const float* b1  = (const float*)d_in[7];
    const float* W2  = (const float*)d_in[8];
    const float* b2  = (const float*)d_in[9];
    const float* Wrr = (const float*)d_in[10];
    const float* brr = (const float*)d_in[11];
    const float* Wrc = (const float*)d_in[12];
    const float* brc = (const float*)d_in[13];
    const int E = in_sizes[1];

    int sms = 148;
    cudaDeviceGetAttribute(&sms, cudaDevAttrMultiProcessorCount, 0);
    cudaFuncSetAttribute(attr_rel_kernel,
                         cudaFuncAttributeMaxDynamicSharedMemorySize, SMEM_BYTES);

    attr_rel_kernel<<<sms, NTHREADS, SMEM_BYTES>>>(
        known_mask, obs_idx, obs_mask_idx, attr_idx, obs_embs, fea_corr,
        W1, b1, W2, b2, Wrr, brr, Wrc, brc,
        (float*)d_out, E);
}